// round 13
// baseline (speedup 1.0000x reference)
#include <cuda_runtime.h>
#include <cstdint>
#include <cstddef>

#define BB 64
#define LL 1024
#define HH 64
#define LM1 1023
#define CH 32            // scan staging chunk (steps)
#define TPC 128          // tokens per CTA in k_tokens
#define RP 132           // padded row length (floats) for transposed smem tiles

// Scratch (device globals — the allowed scratch mechanism). Zero-initialized.
__device__ float g_k   [BB * LM1 * HH + 4 * HH];  // pre-normalized keys (+pad for Gram/lookahead reads)
__device__ float g_v   [BB * LM1 * HH + 2 * HH];  // values
__device__ float g_ven [BB * 1024];               // 0.16*||v||^2
__device__ float g_gam1[BB * 1024];               // <kn_t, kn_{t+1}>
__device__ float g_gam2[BB * 1024];               // <kn_t, kn_{t+2}>
__device__ float g_gam3[BB * 1024];               // <kn_t, kn_{t+3}>
__device__ float g_q   [BB * HH];

// Packed f32x2 FMA
__device__ __forceinline__ float2 fma2(float2 a, float2 b, float2 c) {
    float2 d;
    asm("fma.rn.f32x2 %0, %1, %2, %3;"
        : "=l"(*reinterpret_cast<unsigned long long*>(&d))
        : "l"(*reinterpret_cast<unsigned long long*>(&a)),
          "l"(*reinterpret_cast<unsigned long long*>(&b)),
          "l"(*reinterpret_cast<unsigned long long*>(&c)));
    return d;
}

__device__ __forceinline__ void cp16(uint32_t dst, const void* src) {
    asm volatile("cp.async.cg.shared.global [%0], [%1], 16;" :: "r"(dst), "l"(src));
}

// Shared-memory float offsets for k_tokens (total 50496 floats = 197.25 KB)
#define OFF_WA   0
#define OFF_WB   8192
#define OFF_HT   16384
#define OFF_ST   24832
#define OFF_FFT  41728
#define OFF_B1   50176
#define OFF_B2   50304
#define OFF_G    50368
#define OFF_BT   50432
#define SMEM_TOK_FLOATS 50496

// ---------------------------------------------------------------------------
// Kernel 1: cooperative register-tiled GEMM pipeline (R8, proven ~100us).
// ---------------------------------------------------------------------------
__global__ __launch_bounds__(256, 1)
void k_tokens(const int*   __restrict__ seq,
              const float* __restrict__ embedW,
              const float* __restrict__ W1,
              const float* __restrict__ b1,
              const float* __restrict__ W2,
              const float* __restrict__ b2,
              const float* __restrict__ lng,
              const float* __restrict__ lnb,
              const float* __restrict__ kpW,
              const float* __restrict__ vpW,
              const float* __restrict__ qpW)
{
    extern __shared__ float sm[];
    const int tid = threadIdx.x;
    const int cta = blockIdx.x;
    const int b = cta >> 3;
    const int tbase = (cta & 7) * TPC;

    const uint32_t smA = (uint32_t)__cvta_generic_to_shared(sm + OFF_WA);
    const uint32_t smB = (uint32_t)__cvta_generic_to_shared(sm + OFF_WB);

    #pragma unroll
    for (int r = 0; r < 8; r++) {
        cp16(smA + (tid + 256 * r) * 16, (const char*)W1 + (tid + 256 * r) * 16);
        cp16(smB + (tid + 256 * r) * 16, (const char*)W2 + (tid + 256 * r) * 16);
    }
    asm volatile("cp.async.commit_group;" ::: "memory");

    if (tid < 128) sm[OFF_B1 + tid] = b1[tid];
    if (tid < 64) {
        sm[OFF_B2 + tid] = b2[tid];
        sm[OFF_G  + tid] = lng[tid];
        sm[OFF_BT + tid] = lnb[tid];
    }

    const int tok  = tid >> 1;
    const int half = tid & 1;
    {
        const int sidx = seq[(b << 10) + tbase + tok];
        const float4* e4 = reinterpret_cast<const float4*>(embedW + (sidx << 6) + half * 32);
        float* ht = sm + OFF_HT;
        #pragma unroll
        for (int r = 0; r < 8; r++) {
            float4 w = e4[r];
            int k = half * 32 + r * 4;
            ht[(k + 0) * RP + tok] = w.x;
            ht[(k + 1) * RP + tok] = w.y;
            ht[(k + 2) * RP + tok] = w.z;
            ht[(k + 3) * RP + tok] = w.w;
        }
    }
    asm volatile("cp.async.wait_group 0;" ::: "memory");
    __syncthreads();

    // ---- GEMM1 -----------------------------------------------------------
    {
        const int m0 = (tid & 15) * 8;
        const int n0 = (tid >> 4) * 8;
        float2 c1[8][4];
        #pragma unroll
        for (int ni = 0; ni < 8; ni++)
            #pragma unroll
            for (int mj = 0; mj < 4; mj++) c1[ni][mj] = make_float2(0.f, 0.f);

        const float4* ht4 = reinterpret_cast<const float4*>(sm + OFF_HT);
        const float4* w14 = reinterpret_cast<const float4*>(sm + OFF_WA);
        #pragma unroll 4
        for (int k = 0; k < 64; k++) {
            const float4 a0 = ht4[k * (RP / 4) + m0 / 4];
            const float4 a1 = ht4[k * (RP / 4) + m0 / 4 + 1];
            const float2 am[4] = { {a0.x, a0.y}, {a0.z, a0.w}, {a1.x, a1.y}, {a1.z, a1.w} };
            const float4 b0 = w14[k * 32 + n0 / 4];
            const float4 bq = w14[k * 32 + n0 / 4 + 1];
            const float bn[8] = { b0.x, b0.y, b0.z, b0.w, bq.x, bq.y, bq.z, bq.w };
            #pragma unroll
            for (int ni = 0; ni < 8; ni++) {
                const float2 bb = make_float2(bn[ni], bn[ni]);
                #pragma unroll
                for (int mj = 0; mj < 4; mj++)
                    c1[ni][mj] = fma2(bb, am[mj], c1[ni][mj]);
            }
        }
        float4* st4 = reinterpret_cast<float4*>(sm + OFF_ST);
        #pragma unroll
        for (int ni = 0; ni < 8; ni++) {
            const float bb = sm[OFF_B1 + n0 + ni];
            float2 r0 = c1[ni][0], r1 = c1[ni][1], r2 = c1[ni][2], r3 = c1[ni][3];
            r0.x = fmaxf(r0.x + bb, 0.f); r0.y = fmaxf(r0.y + bb, 0.f);
            r1.x = fmaxf(r1.x + bb, 0.f); r1.y = fmaxf(r1.y + bb, 0.f);
            r2.x = fmaxf(r2.x + bb, 0.f); r2.y = fmaxf(r2.y + bb, 0.f);
            r3.x = fmaxf(r3.x + bb, 0.f); r3.y = fmaxf(r3.y + bb, 0.f);
            st4[(n0 + ni) * (RP / 4) + m0 / 4]     = make_float4(r0.x, r0.y, r1.x, r1.y);
            st4[(n0 + ni) * (RP / 4) + m0 / 4 + 1] = make_float4(r2.x, r2.y, r3.x, r3.y);
        }
    }
    __syncthreads();

    // ---- prefetch KV-combined weights [64][128] (2048 float4s) -----------
    {
        #pragma unroll
        for (int r = 0; r < 8; r++) {
            const int f = tid + 256 * r;
            const int k = f >> 5;
            const int c4 = f & 31;
            const char* src = (c4 < 16)
                ? (const char*)kpW + (k * 16 + c4) * 16
                : (const char*)vpW + (k * 16 + (c4 - 16)) * 16;
            cp16(smA + f * 16, src);
        }
        asm volatile("cp.async.commit_group;" ::: "memory");
    }

    // ---- GEMM2 -----------------------------------------------------------
    {
        const int m0 = (tid >> 4) * 8;
        const int n0 = (tid & 15) * 4;
        float2 c2[4][4];
        #pragma unroll
        for (int ni = 0; ni < 4; ni++)
            #pragma unroll
            for (int mj = 0; mj < 4; mj++) c2[ni][mj] = make_float2(0.f, 0.f);

        const float4* st4 = reinterpret_cast<const float4*>(sm + OFF_ST);
        const float4* w24 = reinterpret_cast<const float4*>(sm + OFF_WB);
        #pragma unroll 4
        for (int k = 0; k < 128; k++) {
            const float4 a0 = st4[k * (RP / 4) + m0 / 4];
            const float4 a1 = st4[k * (RP / 4) + m0 / 4 + 1];
            const float2 am[4] = { {a0.x, a0.y}, {a0.z, a0.w}, {a1.x, a1.y}, {a1.z, a1.w} };
            const float4 b0 = w24[k * 16 + n0 / 4];
            const float bn[4] = { b0.x, b0.y, b0.z, b0.w };
            #pragma unroll
            for (int ni = 0; ni < 4; ni++) {
                const float2 bb = make_float2(bn[ni], bn[ni]);
                #pragma unroll
                for (int mj = 0; mj < 4; mj++)
                    c2[ni][mj] = fma2(bb, am[mj], c2[ni][mj]);
            }
        }
        float4* ff4 = reinterpret_cast<float4*>(sm + OFF_FFT);
        #pragma unroll
        for (int ni = 0; ni < 4; ni++) {
            const float bb = sm[OFF_B2 + n0 + ni];
            float2 r0 = c2[ni][0], r1 = c2[ni][1], r2 = c2[ni][2], r3 = c2[ni][3];
            r0.x += bb; r0.y += bb; r1.x += bb; r1.y += bb;
            r2.x += bb; r2.y += bb; r3.x += bb; r3.y += bb;
            ff4[(n0 + ni) * (RP / 4) + m0 / 4]     = make_float4(r0.x, r0.y, r1.x, r1.y);
            ff4[(n0 + ni) * (RP / 4) + m0 / 4 + 1] = make_float4(r2.x, r2.y, r3.x, r3.y);
        }
    }
    __syncthreads();

    // ---- LayerNorm per token ---------------------------------------------
    {
        float x[32];
        const float* ht = sm + OFF_HT;
        const float* ff = sm + OFF_FFT;
        #pragma unroll
        for (int j = 0; j < 32; j++) {
            const int k = half * 32 + j;
            x[j] = ht[k * RP + tok] + ff[k * RP + tok];
        }
        float s1 = 0.f;
        #pragma unroll
        for (int j = 0; j < 32; j++) s1 += x[j];
        s1 += __shfl_xor_sync(0xffffffffu, s1, 1);
        const float mu = s1 * (1.0f / 64.0f);
        float s2 = 0.f;
        #pragma unroll
        for (int j = 0; j < 32; j++) { const float dx = x[j] - mu; s2 += dx * dx; }
        s2 += __shfl_xor_sync(0xffffffffu, s2, 1);
        const float inv = 1.0f / sqrtf(s2 * (1.0f / 64.0f) + 1e-5f);
        float* hw = sm + OFF_HT;
        #pragma unroll
        for (int j = 0; j < 32; j++) {
            const int k = half * 32 + j;
            hw[k * RP + tok] = (x[j] - mu) * inv * sm[OFF_G + k] + sm[OFF_BT + k];
        }
    }
    asm volatile("cp.async.wait_group 0;" ::: "memory");
    __syncthreads();

    // ---- GEMM3: K|V ------------------------------------------------------
    {
        const int m0 = (tid & 15) * 8;
        const int n0 = (tid >> 4) * 8;
        float2 c3[8][4];
        #pragma unroll
        for (int ni = 0; ni < 8; ni++)
            #pragma unroll
            for (int mj = 0; mj < 4; mj++) c3[ni][mj] = make_float2(0.f, 0.f);

        const float4* ht4 = reinterpret_cast<const float4*>(sm + OFF_HT);
        const float4* wk4 = reinterpret_cast<const float4*>(sm + OFF_WA);
        #pragma unroll 4
        for (int k = 0; k < 64; k++) {
            const float4 a0 = ht4[k * (RP / 4) + m0 / 4];
            const float4 a1 = ht4[k * (RP / 4) + m0 / 4 + 1];
            const float2 am[4] = { {a0.x, a0.y}, {a0.z, a0.w}, {a1.x, a1.y}, {a1.z, a1.w} };
            const float4 b0 = wk4[k * 32 + n0 / 4];
            const float4 bq = wk4[k * 32 + n0 / 4 + 1];
            const float bn[8] = { b0.x, b0.y, b0.z, b0.w, bq.x, bq.y, bq.z, bq.w };
            #pragma unroll
            for (int ni = 0; ni < 8; ni++) {
                const float2 bb = make_float2(bn[ni], bn[ni]);
                #pragma unroll
                for (int mj = 0; mj < 4; mj++)
                    c3[ni][mj] = fma2(bb, am[mj], c3[ni][mj]);
            }
        }
        float4* kv4 = reinterpret_cast<float4*>(sm + OFF_ST);
        #pragma unroll
        for (int ni = 0; ni < 8; ni++) {
            const float2 r0 = c3[ni][0], r1 = c3[ni][1], r2 = c3[ni][2], r3 = c3[ni][3];
            kv4[(n0 + ni) * (RP / 4) + m0 / 4]     = make_float4(r0.x, r0.y, r1.x, r1.y);
            kv4[(n0 + ni) * (RP / 4) + m0 / 4 + 1] = make_float4(r2.x, r2.y, r3.x, r3.y);
        }
    }
    __syncthreads();

    // ---- k-normalize, ven, stores ----------------------------------------
    {
        const int t = tbase + tok;
        const float* kv = sm + OFF_ST;
        float kvv[32];
        float nk = 0.f;
        #pragma unroll
        for (int j = 0; j < 32; j++) {
            kvv[j] = kv[(half * 32 + j) * RP + tok];
            nk = fmaf(kvv[j], kvv[j], nk);
        }
        nk += __shfl_xor_sync(0xffffffffu, nk, 1);
        const float kinv = 1.0f / fmaxf(sqrtf(nk), 1e-12f);
        if (t < LM1) {
            const size_t base = ((size_t)(b * LM1 + t)) << 6;
            float4* gk4 = reinterpret_cast<float4*>(g_k + base + half * 32);
            #pragma unroll
            for (int j4 = 0; j4 < 8; j4++) {
                gk4[j4] = make_float4(kvv[4 * j4] * kinv, kvv[4 * j4 + 1] * kinv,
                                      kvv[4 * j4 + 2] * kinv, kvv[4 * j4 + 3] * kinv);
            }
        }
        float nv = 0.f;
        #pragma unroll
        for (int j = 0; j < 32; j++) {
            kvv[j] = kv[(64 + half * 32 + j) * RP + tok];
            nv = fmaf(kvv[j], kvv[j], nv);
        }
        const float nvt = nv + __shfl_xor_sync(0xffffffffu, nv, 1);
        if (t < LM1) {
            const size_t base = ((size_t)(b * LM1 + t)) << 6;
            float4* gv4 = reinterpret_cast<float4*>(g_v + base + half * 32);
            #pragma unroll
            for (int j4 = 0; j4 < 8; j4++) {
                gv4[j4] = make_float4(kvv[4 * j4], kvv[4 * j4 + 1],
                                      kvv[4 * j4 + 2], kvv[4 * j4 + 3]);
            }
            if (half == 0) g_ven[(b << 10) + t] = 0.16f * nvt;
        }
    }

    // ---- q projection ----------------------------------------------------
    if ((cta & 7) == 7 && tid < 64) {
        const float* ht = sm + OFF_HT;
        float a0 = 0.f, a1 = 0.f, a2 = 0.f, a3 = 0.f;
        #pragma unroll 8
        for (int k = 0; k < 64; k += 4) {
            a0 = fmaf(ht[(k + 0) * RP + 127], __ldg(qpW + (k + 0) * 64 + tid), a0);
            a1 = fmaf(ht[(k + 1) * RP + 127], __ldg(qpW + (k + 1) * 64 + tid), a1);
            a2 = fmaf(ht[(k + 2) * RP + 127], __ldg(qpW + (k + 2) * 64 + tid), a2);
            a3 = fmaf(ht[(k + 3) * RP + 127], __ldg(qpW + (k + 3) * 64 + tid), a3);
        }
        g_q[(b << 6) + tid] = (a0 + a1) + (a2 + a3);
    }
}

// ---------------------------------------------------------------------------
// Kernel 1b: key Gram at distances 1..3.
// ---------------------------------------------------------------------------
__global__ __launch_bounds__(256, 1)
void k_gamma()
{
    const int idx = blockIdx.x * 256 + threadIdx.x;
    const int b = idx >> 10;
    const int t = idx & 1023;
    float d1 = 0.f, d2 = 0.f, d3 = 0.f;
    if (t <= 1022) {
        const float4* a = reinterpret_cast<const float4*>(g_k + (((size_t)(b * LM1 + t)) << 6));
        #pragma unroll
        for (int k = 0; k < 16; k++) {
            const float4 x = a[k];
            const float4 y1 = a[k + 16];
            const float4 y2 = a[k + 32];
            const float4 y3 = a[k + 48];
            d1 = fmaf(x.x, y1.x, fmaf(x.y, y1.y, fmaf(x.z, y1.z, fmaf(x.w, y1.w, d1))));
            d2 = fmaf(x.x, y2.x, fmaf(x.y, y2.y, fmaf(x.z, y2.z, fmaf(x.w, y2.w, d2))));
            d3 = fmaf(x.x, y3.x, fmaf(x.y, y3.y, fmaf(x.z, y3.z, fmaf(x.w, y3.w, d3))));
        }
    }
    g_gam1[(b << 10) + t] = (t <= 1021) ? d1 : 0.f;
    g_gam2[(b << 10) + t] = (t <= 1020) ? d2 : 0.f;
    g_gam3[(b << 10) + t] = (t <= 1019) ? d3 : 0.f;
}

// ---------------------------------------------------------------------------
// Kernel 2: gated fast-weight scan — 2-step blocks, STALE-M LOOKAHEAD, 64thr.
// Block j (steps t=2j, t+1). State entering block j:
//   ep0,ep1 = raw residuals v - M_{block j-2 end} * kn  for steps t, t+1
//   gdA,gdB = gated d's of block j-1 (steps t-2, t-1)
// Serial: e = ep - gdA*G(.) - gdB*G(.)  (4 fma, Grams precomputed)
//         -> (D,E,C) 15-shfl tree -> bar -> R9 2-gate resolve.
// Batch (gate-independent, overlaps tree): apply gdA,gdB updates -> M;
//         raw residuals for block j+1 (keys t+2,t+3).
// ---------------------------------------------------------------------------
__global__ __launch_bounds__(64, 1)
void k_scan(const float* __restrict__ rpW,
            const float* __restrict__ rpb,
            const float* __restrict__ outW,
            const float* __restrict__ outb,
            float* __restrict__ out)
{
    __shared__ float  sK[2 * CH][64];
    __shared__ float  sV[2 * CH][64];
    __shared__ float  sVen[2 * CH];
    __shared__ float  sG1[2 * CH];
    __shared__ float  sG2[2 * CH];
    __shared__ float  sG3[2 * CH];
    __shared__ float4 sred[2][2];     // (D,E,C,-) per warp, parity-buffered
    __shared__ float  sq[64];
    __shared__ float  sr[64];

    const int i = threadIdx.x;
    const int b = blockIdx.x;
    const int lane = i & 31, w = i >> 5;

    const size_t base = (size_t)b * LM1 * 64;
    const int vb = b << 10;

    const uint32_t aK   = (uint32_t)__cvta_generic_to_shared(&sK[0][0]);
    const uint32_t aV   = (uint32_t)__cvta_generic_to_shared(&sV[0][0]);
    const uint32_t aVen = (uint32_t)__cvta_generic_to_shared(&sVen[0]);
    const uint32_t aG1  = (uint32_t)__cvta_generic_to_shared(&sG1[0]);
    const uint32_t aG2  = (uint32_t)__cvta_generic_to_shared(&sG2[0]);
    const uint32_t aG3  = (uint32_t)__cvta_generic_to_shared(&sG3[0]);

    auto stage = [&](int q) {
        const int hb = (q & 1) * (CH * 64 * 4);
        const int hs = (q & 1) * (CH * 4);
        const char* gk = (const char*)(g_k + base) + ((size_t)q << 13);
        const char* gv = (const char*)(g_v + base) + ((size_t)q << 13);
        #pragma unroll
        for (int r = 0; r < 8; r++) {
            cp16(aK + hb + i * 16 + r * 1024, gk + i * 16 + r * 1024);
            cp16(aV + hb + i * 16 + r * 1024, gv + i * 16 + r * 1024);
        }
        if (i < 8)       cp16(aVen + hs + i * 16,        (const char*)(g_ven  + vb + q * CH) + i * 16);
        else if (i < 16) cp16(aG1  + hs + (i - 8) * 16,  (const char*)(g_gam1 + vb + q * CH) + (i - 8) * 16);
        else if (i < 24) cp16(aG2  + hs + (i - 16) * 16, (const char*)(g_gam2 + vb + q * CH) + (i - 16) * 16);
        else if (i < 32) cp16(aG3  + hs + (i - 24) * 16, (const char*)(g_gam3 + vb + q * CH) + (i - 24) * 16);
        asm volatile("cp.async.commit_group;" ::: "memory");
    };

    float2 M[32];
    #pragma unroll
    for (int c = 0; c < 32; c++) M[c] = make_float2(0.f, 0.f);

    stage(0);
    asm volatile("cp.async.wait_group 0;" ::: "memory");
    __syncthreads();

    // ---- prologue: block 0 raw residuals (M=0 -> ep = v), no pending gd --
    float ep0 = sV[0][i], ep1 = sV[1][i];
    float gdA = 0.f, gdB = 0.f;

    // ---- main loop: 511 blocks of 2 steps, t = 0,2,...,1020 ---------------
    for (int j = 0; j < 511; j++) {
        const int t = 2 * j;
        if ((t & 31) == 30) {                 // batch reads keys t+2,t+3 in next chunk
            asm volatile("cp.async.wait_group 0;" ::: "memory");
            __syncthreads();
        }
        if ((t & 31) == 2) {
            const int qn = (t >> 5) + 1;
            if (qn < 32) stage(qn);
        }

        const int sA = j ? ((t - 2) & 63) : 0;
        const int sB = j ? ((t - 1) & 63) : 0;
        const int sT = t & 63, sU = (t + 1) & 63;
        const int sN0 = (t + 2) & 63, sN1 = (t + 3) & 63;

        // ---- serial: Gram corrections (cheap) ----------------------------
        float e0, e1;
        if (j) {
            e0 = ep0 - (gdA * sG2[sA] + gdB * sG1[sB]);
            e1 = ep1 - (gdA * sG3[sA] + gdB * sG2[sB]);
        } else { e0 = ep0; e1 = ep1; }

        // ---- serial: (D,E,C) tree — 15 shfl ------------------------------
        float D = e0 * e0;
        float E = e1 * e1;
        float C = e0 * e1;
        #pragma unroll
        for (int o = 1; o <= 16; o <<= 1) {
            D += __shfl_xor_sync(0xffffffffu, D, o);
            E += __shfl_xor_sync(0xffffffffu, E, o);
            C += __shfl_xor_sync(0xffffffffu, C, o);
        }
        const int pb = j & 1;
        if (lane == 0) sred[pb][w] = make_float4(D, E, C, 0.f);

        // ---- batch (gate-independent; overlaps the tree) -----------------
        // 1) apply block j-1's updates -> M_{t-1}
        {
            const float4* kA = reinterpret_cast<const float4*>(sK[sA]);
            const float4* kB = reinterpret_cast<const float4*>(sK[sB]);
            const float2 ga = make_float2(gdA, gdA);
            const float2 gb = make_float2(gdB, gdB);
            #pragma unroll
            for (int c = 0; c < 16; c++) {
                const float4 a = kA[c];
                const float4 bq = kB[c];
                float2 m0 = M[2 * c], m1 = M[2 * c + 1];
                m0 = fma2(ga, make_float2(a.x, a.y), m0);
                m1 = fma2(ga, make_float2(a.z, a.w), m1);
                m0 = fma2(gb, make_float2(bq.x, bq.y), m0);
                m1 = fma2(gb, make_float2(bq.z, bq.w), m1);
                M[2 * c] = m0; M[2 * c + 1] = m1;
            }
        }
        // 2) raw residuals for block j+1 (keys t+2,t+3; padded OOB-safe)
        float ep0n, ep1n;
        {
            const float4* k0 = reinterpret_cast<const float4*>(sK[sN0]);
            const float4* k1 = reinterpret_cast<const float4*>(sK[sN1]);
            float2 u0 = make_float2(0.f, 0.f), u1 = u0, u2 = u0, u3 = u0;
            #pragma unroll
            for (int c = 0; c < 16; c += 2) {
                const float4 a = k0[c];
                const float4 bq = k0[c + 1];
                u0 = fma2(M[2 * c],     make_float2(a.x, a.y),  u0);
                u1 = fma2(M[2 * c + 1], make_float2(a.z, a.w),  u1);
                u0 = fma2(M[2 * c + 2], make_float2(bq.x, bq.y), u0);
                u1 = fma2(M[2 * c + 3], make_float2(bq.z, bq.w), u1);
                const float4 a2 = k1[c];
                const float4 b2 = k1[c + 1];
                u2 = fma2(M[2 * c],     make_float2(a2.x, a2.y), u2);
                u3 = fma2(M[2 * c + 1], make_float2(a2.z, a2.w), u3);
                u2 = fma2(M[2 * c + 2], make_float2(b2.x, b2.y), u2);
                u3 = fma2(M[2 * c + 3], make_float2(b2.z, b2.w), u3);
            }
            ep0n = sV[sN0][i] - ((u0.x + u0.y) + (u1.x + u1.y));
            ep1n = sV[sN1][i] - ((u2.x + u2.y) + (u3.x + u3.y));
        }

        __syncthreads();                      // the ONLY barrier per 2 steps

        // ---- combine + resolve (R9 algebra verbatim) ---------------------
        const float4 r0 = sred[pb][0];
        const float4 r1 = sred[pb][1];
        const float Dt = r0.x + r1.x;
        const float Et = r0.y + r1.y;
        const float Ct = r0.z + r1.z;

        const float gam = sG1[sT];
        const bool g0 = Dt > sVen[sT];
        const float a = g0 ? gam : 0.0f;
        const float z2 = fmaf(a, fmaf(gam, Dt, -2.0f * Ct), Et);
        const bool g1 = z2 > sVen[sU];
        gdA = g0 ? e0 : 0.0f;
        const float d1 = fmaf(-a, e0, e1);    // exact per-component d_{t+1}
        gdB = g1 ? d1 : 0.0f;

        ep0 = ep0n; ep1 = ep1n;
    }

    // ---- tail: step 1022 --------------------------------------------------
    {
        const int sA = 1020 & 63, sB = 1021 & 63, sT = 1022 & 63;
        const float e0 = ep0 - (gdA * sG2[sA] + gdB * sG1[sB]);

        float D = e0 * e0;
        #pragma unroll
        for (int o = 1; o <= 16; o <<= 1) D += __shfl_xor_sync(0xffffffffu, D, o);
        if (lane == 0) sred[1][w] = make_float4(D, 0.f, 0.f, 0.f);

        // batch: apply pending updates (keys 1020, 1021)
        {
            const float4* kA = reinterpret_cast<const float4*>(sK[sA]);
            const float4* kB = reinterpret_cast<const float4*>(sK[sB]);
            const float2 ga = make_float2(gdA, gdA);
            const float2 gb = make_float2(gdB, gdB);
            #pragma unroll
            for (int c = 0; c < 16; c++) {
                const float4 a = kA[c];
                const float4 bq = kB[c];
                float2 m0 = M[2 * c], m1 = M[2 * c + 1];
                m0 = fma2(ga, make_float2(a.x, a.y), m0);
                m1 = fma2(ga, make_float2(a.z, a.w), m1);
                m0 = fma2(gb, make_float2(bq.x, bq.y), m0);
                m1 = fma2(gb, make_float2(bq.z, bq.w), m1);
                M[2 * c] = m0; M[2 * c + 1] = m1;
            }
        }
        __syncthreads();
        const float Dt = sred[1][0].x + sred[1][1].x;
        const bool g = Dt > sVen[sT];
        const float gd = g ? e0 : 0.f;

        const float4* kT = reinterpret_cast<const float4*>(sK[sT]);
        const float2 gg = make_float2(gd, gd);
        #pragma unroll
        for (int c = 0; c < 16; c++) {
            const float4 a = kT[c];
            M[2 * c]     = fma2(gg, make_float2(a.x, a.y), M[2 * c]);
            M[2 * c + 1] = fma2(gg, make_float2(a.z, a.w), M[2 * c + 1]);
        }
    }

    // -------- epilogue ----------------------------------------------------
    __syncthreads();
    sq[i] = g_q[(b << 6) + i];
    __syncthreads();
    float mq;
    {
        const float4* qp = reinterpret_cast<const float4*>(sq);
        float2 p0 = make_float2(0.f, 0.f), p1 = p0, p2 = p0, p3 = p0;
        #pragma unroll
        for (int c = 0; c < 16; c += 2) {
            const float4 wa = qp[c];
            const float4 wb = qp[c + 1];
            p0 = fma2(M[2 * c],     make_float2(wa.x, wa.y), p0);
            p1 = fma2(M[2 * c + 1], make_float2(wa.z, wa.w), p1);
            p2 = fma2(M[2 * c + 2], make_float2(wb.x, wb.y), p2);
            p3 = fma2(M[2 * c + 3], make_float2(wb.z, wb.w), p3);
        }
        mq = ((p0.x + p0.y) + (p1.x + p1.y)) + ((p2.x + p2.y) + (p3.x + p3.y));
    }
    __syncthreads();
    sr[i] = mq;
    __syncthreads();
    float r = rpb[i];
    for (int jj = 0; jj < 64; jj++) r = fmaf(sr[jj], rpW[jj * 64 + i], r);
    __syncthreads();
    sr[i] = r;
    __syncthreads();
    float o = outb[i];
    for (int jj = 0; jj < 64; jj++) o = fmaf(sr[jj], outW[jj * 64 + i], o);
    out[(b << 6) + i] = o;
}

// ---------------------------------------------------------------------------
extern "C" void kernel_launch(void* const* d_in, const int* in_sizes, int n_in,
                              void* d_out, int out_size)
{
    const int*   seq    = (const int*)  d_in[0];
    const float* embedW = (const float*)d_in[1];
    const float* W1     = (const float*)d_in[2];
    const float* b1     = (const float*)d_in[3];
    const float* W2     = (const float*)d_in[4];
    const float* b2     = (const float*)d_in[5];
    const float* lng    = (const float*)d_in[6];
    const float* lnb    = (const float*)d_in[7];
    const float* kpW    = (const float*)d_in[8];
    const float* vpW    = (const float*)d_in[9];
    const float* qpW    = (const float*)d_in[10];
    const float* rpW    = (const float*)d_in[11];
    const float* rpb    = (const float*)d_in[12];
    const float* outW   = (const float*)d_in[13];
    const float* outb   = (const float*)d_in[14];
    float* out = (float*)d_out;

    const int smem = SMEM_TOK_FLOATS * (int)sizeof(float);   // 201984 B
    cudaFuncSetAttribute(k_tokens, cudaFuncAttributeMaxDynamicSharedMemorySize, smem);

    k_tokens<<<512, 256, smem>>>(seq, embedW, W1, b1, W2, b2, lng, lnb, kpW, vpW, qpW);
    k_gamma<<<256, 256>>>();
    k_scan<<<64, 64>>>(rpW, rpb, outW, outb, out);
}

// round 14
// speedup vs baseline: 1.1407x; 1.1407x over previous
#include <cuda_runtime.h>
#include <cstdint>
#include <cstddef>

#define BB 64
#define LL 1024
#define HH 64
#define LM1 1023
#define CH 32            // scan staging chunk (steps)
#define TPC 128          // tokens per CTA in k_tokens
#define RP 132           // padded row length (floats) for transposed smem tiles

// Scratch (device globals — the allowed scratch mechanism). Zero-initialized.
__device__ float g_k  [BB * LM1 * HH + 2 * HH];   // pre-normalized keys (row-major)
__device__ float g_v  [BB * LM1 * HH + 2 * HH];   // values (row-major)
__device__ float g_ven[BB * 1024];                // 0.16*||v||^2
__device__ float g_gam[BB * 1024];                // gamma_t = kn_t . kn_{t+1}
__device__ float g_q  [BB * HH];

// Packed f32x2 FMA
__device__ __forceinline__ float2 fma2(float2 a, float2 b, float2 c) {
    float2 d;
    asm("fma.rn.f32x2 %0, %1, %2, %3;"
        : "=l"(*reinterpret_cast<unsigned long long*>(&d))
        : "l"(*reinterpret_cast<unsigned long long*>(&a)),
          "l"(*reinterpret_cast<unsigned long long*>(&b)),
          "l"(*reinterpret_cast<unsigned long long*>(&c)));
    return d;
}

__device__ __forceinline__ void cp16(uint32_t dst, const void* src) {
    asm volatile("cp.async.cg.shared.global [%0], [%1], 16;" :: "r"(dst), "l"(src));
}

// Shared-memory float offsets for k_tokens (total 50496 floats = 197.25 KB)
#define OFF_WA   0        /* 8192: W1 [64][128], later KV-combined [64][128] */
#define OFF_WB   8192     /* 8192: W2 [128][64] */
#define OFF_HT   16384    /* 8448: h^T / hn^T  [64][RP] */
#define OFF_ST   24832    /* 16896: s^T / kv^T [128][RP] */
#define OFF_FFT  41728    /* 8448: ff^T [64][RP] */
#define OFF_B1   50176    /* 128 */
#define OFF_B2   50304    /* 64 */
#define OFF_G    50368    /* 64 */
#define OFF_BT   50432    /* 64 */
#define SMEM_TOK_FLOATS 50496

// ---------------------------------------------------------------------------
// Kernel 1: cooperative register-tiled GEMM pipeline.
// 128 tokens/CTA, 256 threads. grid = 512 (B*L/TPC).
// ---------------------------------------------------------------------------
__global__ __launch_bounds__(256, 1)
void k_tokens(const int*   __restrict__ seq,
              const float* __restrict__ embedW,
              const float* __restrict__ W1,   // [64][128]
              const float* __restrict__ b1,   // [128]
              const float* __restrict__ W2,   // [128][64]
              const float* __restrict__ b2,   // [64]
              const float* __restrict__ lng,
              const float* __restrict__ lnb,
              const float* __restrict__ kpW,  // [64][64]
              const float* __restrict__ vpW,  // [64][64]
              const float* __restrict__ qpW)  // [64][64]
{
    extern __shared__ float sm[];
    const int tid = threadIdx.x;
    const int cta = blockIdx.x;
    const int b = cta >> 3;
    const int tbase = (cta & 7) * TPC;

    const uint32_t smA = (uint32_t)__cvta_generic_to_shared(sm + OFF_WA);
    const uint32_t smB = (uint32_t)__cvta_generic_to_shared(sm + OFF_WB);

    #pragma unroll
    for (int r = 0; r < 8; r++) {
        cp16(smA + (tid + 256 * r) * 16, (const char*)W1 + (tid + 256 * r) * 16);
        cp16(smB + (tid + 256 * r) * 16, (const char*)W2 + (tid + 256 * r) * 16);
    }
    asm volatile("cp.async.commit_group;" ::: "memory");

    if (tid < 128) sm[OFF_B1 + tid] = b1[tid];
    if (tid < 64) {
        sm[OFF_B2 + tid] = b2[tid];
        sm[OFF_G  + tid] = lng[tid];
        sm[OFF_BT + tid] = lnb[tid];
    }

    const int tok  = tid >> 1;
    const int half = tid & 1;
    {
        const int sidx = seq[(b << 10) + tbase + tok];
        const float4* e4 = reinterpret_cast<const float4*>(embedW + (sidx << 6) + half * 32);
        float* ht = sm + OFF_HT;
        #pragma unroll
        for (int r = 0; r < 8; r++) {
            float4 w = e4[r];
            int k = half * 32 + r * 4;
            ht[(k + 0) * RP + tok] = w.x;
            ht[(k + 1) * RP + tok] = w.y;
            ht[(k + 2) * RP + tok] = w.z;
            ht[(k + 3) * RP + tok] = w.w;
        }
    }
    asm volatile("cp.async.wait_group 0;" ::: "memory");
    __syncthreads();

    // ---- GEMM1: s[m][n] = relu(h[m][:]@W1[:][n] + b1), write s^T ---------
    {
        const int m0 = (tid & 15) * 8;
        const int n0 = (tid >> 4) * 8;
        float2 c1[8][4];
        #pragma unroll
        for (int ni = 0; ni < 8; ni++)
            #pragma unroll
            for (int mj = 0; mj < 4; mj++) c1[ni][mj] = make_float2(0.f, 0.f);

        const float4* ht4 = reinterpret_cast<const float4*>(sm + OFF_HT);
        const float4* w14 = reinterpret_cast<const float4*>(sm + OFF_WA);
        #pragma unroll 4
        for (int k = 0; k < 64; k++) {
            const float4 a0 = ht4[k * (RP / 4) + m0 / 4];
            const float4 a1 = ht4[k * (RP / 4) + m0 / 4 + 1];
            const float2 am[4] = { {a0.x, a0.y}, {a0.z, a0.w}, {a1.x, a1.y}, {a1.z, a1.w} };
            const float4 b0 = w14[k * 32 + n0 / 4];
            const float4 bq = w14[k * 32 + n0 / 4 + 1];
            const float bn[8] = { b0.x, b0.y, b0.z, b0.w, bq.x, bq.y, bq.z, bq.w };
            #pragma unroll
            for (int ni = 0; ni < 8; ni++) {
                const float2 bb = make_float2(bn[ni], bn[ni]);
                #pragma unroll
                for (int mj = 0; mj < 4; mj++)
                    c1[ni][mj] = fma2(bb, am[mj], c1[ni][mj]);
            }
        }
        float4* st4 = reinterpret_cast<float4*>(sm + OFF_ST);
        #pragma unroll
        for (int ni = 0; ni < 8; ni++) {
            const float bb = sm[OFF_B1 + n0 + ni];
            float2 r0 = c1[ni][0], r1 = c1[ni][1], r2 = c1[ni][2], r3 = c1[ni][3];
            r0.x = fmaxf(r0.x + bb, 0.f); r0.y = fmaxf(r0.y + bb, 0.f);
            r1.x = fmaxf(r1.x + bb, 0.f); r1.y = fmaxf(r1.y + bb, 0.f);
            r2.x = fmaxf(r2.x + bb, 0.f); r2.y = fmaxf(r2.y + bb, 0.f);
            r3.x = fmaxf(r3.x + bb, 0.f); r3.y = fmaxf(r3.y + bb, 0.f);
            st4[(n0 + ni) * (RP / 4) + m0 / 4]     = make_float4(r0.x, r0.y, r1.x, r1.y);
            st4[(n0 + ni) * (RP / 4) + m0 / 4 + 1] = make_float4(r2.x, r2.y, r3.x, r3.y);
        }
    }
    __syncthreads();

    // ---- prefetch KV-combined weights [64][128] (2048 float4s) -----------
    {
        #pragma unroll
        for (int r = 0; r < 8; r++) {
            const int f = tid + 256 * r;        // 0..2047
            const int k = f >> 5;               // 0..63
            const int c4 = f & 31;
            const char* src = (c4 < 16)
                ? (const char*)kpW + (k * 16 + c4) * 16
                : (const char*)vpW + (k * 16 + (c4 - 16)) * 16;
            cp16(smA + f * 16, src);
        }
        asm volatile("cp.async.commit_group;" ::: "memory");
    }

    // ---- GEMM2: ff[m][n] = s[m][:]@W2[:][n] + b2, write ff^T -------------
    {
        const int m0 = (tid >> 4) * 8;
        const int n0 = (tid & 15) * 4;
        float2 c2[4][4];
        #pragma unroll
        for (int ni = 0; ni < 4; ni++)
            #pragma unroll
            for (int mj = 0; mj < 4; mj++) c2[ni][mj] = make_float2(0.f, 0.f);

        const float4* st4 = reinterpret_cast<const float4*>(sm + OFF_ST);
        const float4* w24 = reinterpret_cast<const float4*>(sm + OFF_WB);
        #pragma unroll 4
        for (int k = 0; k < 128; k++) {
            const float4 a0 = st4[k * (RP / 4) + m0 / 4];
            const float4 a1 = st4[k * (RP / 4) + m0 / 4 + 1];
            const float2 am[4] = { {a0.x, a0.y}, {a0.z, a0.w}, {a1.x, a1.y}, {a1.z, a1.w} };
            const float4 b0 = w24[k * 16 + n0 / 4];
            const float bn[4] = { b0.x, b0.y, b0.z, b0.w };
            #pragma unroll
            for (int ni = 0; ni < 4; ni++) {
                const float2 bb = make_float2(bn[ni], bn[ni]);
                #pragma unroll
                for (int mj = 0; mj < 4; mj++)
                    c2[ni][mj] = fma2(bb, am[mj], c2[ni][mj]);
            }
        }
        float4* ff4 = reinterpret_cast<float4*>(sm + OFF_FFT);
        #pragma unroll
        for (int ni = 0; ni < 4; ni++) {
            const float bb = sm[OFF_B2 + n0 + ni];
            float2 r0 = c2[ni][0], r1 = c2[ni][1], r2 = c2[ni][2], r3 = c2[ni][3];
            r0.x += bb; r0.y += bb; r1.x += bb; r1.y += bb;
            r2.x += bb; r2.y += bb; r3.x += bb; r3.y += bb;
            ff4[(n0 + ni) * (RP / 4) + m0 / 4]     = make_float4(r0.x, r0.y, r1.x, r1.y);
            ff4[(n0 + ni) * (RP / 4) + m0 / 4 + 1] = make_float4(r2.x, r2.y, r3.x, r3.y);
        }
    }
    __syncthreads();

    // ---- LayerNorm per token (2 threads/token, partner shfl) -------------
    {
        float x[32];
        const float* ht = sm + OFF_HT;
        const float* ff = sm + OFF_FFT;
        #pragma unroll
        for (int j = 0; j < 32; j++) {
            const int k = half * 32 + j;
            x[j] = ht[k * RP + tok] + ff[k * RP + tok];
        }
        float s1 = 0.f;
        #pragma unroll
        for (int j = 0; j < 32; j++) s1 += x[j];
        s1 += __shfl_xor_sync(0xffffffffu, s1, 1);
        const float mu = s1 * (1.0f / 64.0f);
        float s2 = 0.f;
        #pragma unroll
        for (int j = 0; j < 32; j++) { const float dx = x[j] - mu; s2 += dx * dx; }
        s2 += __shfl_xor_sync(0xffffffffu, s2, 1);
        const float inv = 1.0f / sqrtf(s2 * (1.0f / 64.0f) + 1e-5f);
        float* hw = sm + OFF_HT;
        #pragma unroll
        for (int j = 0; j < 32; j++) {
            const int k = half * 32 + j;
            hw[k * RP + tok] = (x[j] - mu) * inv * sm[OFF_G + k] + sm[OFF_BT + k];
        }
    }
    asm volatile("cp.async.wait_group 0;" ::: "memory");
    __syncthreads();

    // ---- GEMM3: kv[m][n] = hn[m][:]@KV[:][n]  (n<64: K, n>=64: V) --------
    {
        const int m0 = (tid & 15) * 8;
        const int n0 = (tid >> 4) * 8;
        float2 c3[8][4];
        #pragma unroll
        for (int ni = 0; ni < 8; ni++)
            #pragma unroll
            for (int mj = 0; mj < 4; mj++) c3[ni][mj] = make_float2(0.f, 0.f);

        const float4* ht4 = reinterpret_cast<const float4*>(sm + OFF_HT);
        const float4* wk4 = reinterpret_cast<const float4*>(sm + OFF_WA);
        #pragma unroll 4
        for (int k = 0; k < 64; k++) {
            const float4 a0 = ht4[k * (RP / 4) + m0 / 4];
            const float4 a1 = ht4[k * (RP / 4) + m0 / 4 + 1];
            const float2 am[4] = { {a0.x, a0.y}, {a0.z, a0.w}, {a1.x, a1.y}, {a1.z, a1.w} };
            const float4 b0 = wk4[k * 32 + n0 / 4];
            const float4 bq = wk4[k * 32 + n0 / 4 + 1];
            const float bn[8] = { b0.x, b0.y, b0.z, b0.w, bq.x, bq.y, bq.z, bq.w };
            #pragma unroll
            for (int ni = 0; ni < 8; ni++) {
                const float2 bb = make_float2(bn[ni], bn[ni]);
                #pragma unroll
                for (int mj = 0; mj < 4; mj++)
                    c3[ni][mj] = fma2(bb, am[mj], c3[ni][mj]);
            }
        }
        float4* kv4 = reinterpret_cast<float4*>(sm + OFF_ST);
        #pragma unroll
        for (int ni = 0; ni < 8; ni++) {
            const float2 r0 = c3[ni][0], r1 = c3[ni][1], r2 = c3[ni][2], r3 = c3[ni][3];
            kv4[(n0 + ni) * (RP / 4) + m0 / 4]     = make_float4(r0.x, r0.y, r1.x, r1.y);
            kv4[(n0 + ni) * (RP / 4) + m0 / 4 + 1] = make_float4(r2.x, r2.y, r3.x, r3.y);
        }
    }
    __syncthreads();

    // ---- k-normalize, ven, stores (2 threads/token) ----------------------
    {
        const int t = tbase + tok;
        const float* kv = sm + OFF_ST;
        float kvv[32];
        float nk = 0.f;
        #pragma unroll
        for (int j = 0; j < 32; j++) {
            kvv[j] = kv[(half * 32 + j) * RP + tok];
            nk = fmaf(kvv[j], kvv[j], nk);
        }
        nk += __shfl_xor_sync(0xffffffffu, nk, 1);
        const float kinv = 1.0f / fmaxf(sqrtf(nk), 1e-12f);
        if (t < LM1) {
            const size_t base = ((size_t)(b * LM1 + t)) << 6;
            float4* gk4 = reinterpret_cast<float4*>(g_k + base + half * 32);
            #pragma unroll
            for (int j4 = 0; j4 < 8; j4++) {
                gk4[j4] = make_float4(kvv[4 * j4] * kinv, kvv[4 * j4 + 1] * kinv,
                                      kvv[4 * j4 + 2] * kinv, kvv[4 * j4 + 3] * kinv);
            }
        }
        float nv = 0.f;
        #pragma unroll
        for (int j = 0; j < 32; j++) {
            kvv[j] = kv[(64 + half * 32 + j) * RP + tok];
            nv = fmaf(kvv[j], kvv[j], nv);
        }
        const float nvt = nv + __shfl_xor_sync(0xffffffffu, nv, 1);
        if (t < LM1) {
            const size_t base = ((size_t)(b * LM1 + t)) << 6;
            float4* gv4 = reinterpret_cast<float4*>(g_v + base + half * 32);
            #pragma unroll
            for (int j4 = 0; j4 < 8; j4++) {
                gv4[j4] = make_float4(kvv[4 * j4], kvv[4 * j4 + 1],
                                      kvv[4 * j4 + 2], kvv[4 * j4 + 3]);
            }
            if (half == 0) g_ven[(b << 10) + t] = 0.16f * nvt;
        }
    }

    // ---- q projection (only CTAs containing t = 1023; token 127) ---------
    if ((cta & 7) == 7 && tid < 64) {
        const float* ht = sm + OFF_HT;
        float a0 = 0.f, a1 = 0.f, a2 = 0.f, a3 = 0.f;
        #pragma unroll 8
        for (int k = 0; k < 64; k += 4) {
            a0 = fmaf(ht[(k + 0) * RP + 127], __ldg(qpW + (k + 0) * 64 + tid), a0);
            a1 = fmaf(ht[(k + 1) * RP + 127], __ldg(qpW + (k + 1) * 64 + tid), a1);
            a2 = fmaf(ht[(k + 2) * RP + 127], __ldg(qpW + (k + 2) * 64 + tid), a2);
            a3 = fmaf(ht[(k + 3) * RP + 127], __ldg(qpW + (k + 3) * 64 + tid), a3);
        }
        g_q[(b << 6) + tid] = (a0 + a1) + (a2 + a3);
    }
}

// ---------------------------------------------------------------------------
// Kernel 1b: adjacent-key dots  gamma[b][t] = kn_t . kn_{t+1}
// ---------------------------------------------------------------------------
__global__ __launch_bounds__(256, 1)
void k_gamma()
{
    const int idx = blockIdx.x * 256 + threadIdx.x;
    const int b = idx >> 10;
    const int t = idx & 1023;
    float g = 0.0f;
    if (t <= LM1 - 2) {
        const float4* a = reinterpret_cast<const float4*>(g_k + (((size_t)(b * LM1 + t)) << 6));
        const float4* c = a + 16;
        float s0 = 0.f, s1 = 0.f, s2 = 0.f, s3 = 0.f;
        #pragma unroll
        for (int k = 0; k < 16; k += 2) {
            float4 x0 = a[k],     y0 = c[k];
            float4 x1 = a[k + 1], y1 = c[k + 1];
            s0 = fmaf(x0.x, y0.x, fmaf(x0.y, y0.y, s0));
            s1 = fmaf(x0.z, y0.z, fmaf(x0.w, y0.w, s1));
            s2 = fmaf(x1.x, y1.x, fmaf(x1.y, y1.y, s2));
            s3 = fmaf(x1.z, y1.z, fmaf(x1.w, y1.w, s3));
        }
        g = (s0 + s1) + (s2 + s3);
    }
    g_gam[(b << 10) + t] = g;
}

// ---------------------------------------------------------------------------
// Kernel 2: gated fast-weight scan — 2 gates per serial round (R9, best).
// Block (t, t+1): apply pending rank-1 updates for t-2, t-1 -> M_{t-1};
//   d_t = v_t - M_{t-1} kn_t  (exact); e_{t+1} = v_{t+1} - M_{t-1} kn_{t+1};
//   reduce (D,E,C) in ONE tree + ONE barrier;
//   g_t = D > ven_t; z2 = E + a(gam*D - 2C), a = g_t*gam_t; g_{t+1} = z2 > ven_{t+1};
//   d_{t+1} = e - a*d_t per-component (exact M path).
// ---------------------------------------------------------------------------
__global__ __launch_bounds__(64, 1)
void k_scan(const float* __restrict__ rpW,
            const float* __restrict__ rpb,
            const float* __restrict__ outW,
            const float* __restrict__ outb,
            float* __restrict__ out)
{
    __shared__ float  sK[2 * CH][64];
    __shared__ float  sV[2 * CH][64];
    __shared__ float  sVen[2 * CH];
    __shared__ float  sGam[2 * CH];
    __shared__ float4 sred[2][2];     // (D,E,C,-) per warp, parity-buffered
    __shared__ float  sq[64];
    __shared__ float  sr[64];

    const int i = threadIdx.x;
    const int b = blockIdx.x;
    const int lane = i & 31, w = i >> 5;

    const size_t base = (size_t)b * LM1 * 64;
    const int vb = b << 10;

    const uint32_t aK   = (uint32_t)__cvta_generic_to_shared(&sK[0][0]);
    const uint32_t aV   = (uint32_t)__cvta_generic_to_shared(&sV[0][0]);
    const uint32_t aVen = (uint32_t)__cvta_generic_to_shared(&sVen[0]);
    const uint32_t aGam = (uint32_t)__cvta_generic_to_shared(&sGam[0]);

    auto stage = [&](int q) {
        const int hb = (q & 1) * (CH * 64 * 4);
        const int hs = (q & 1) * (CH * 4);
        const char* gk = (const char*)(g_k + base) + ((size_t)q << 13);
        const char* gv = (const char*)(g_v + base) + ((size_t)q << 13);
        #pragma unroll
        for (int r = 0; r < 8; r++) {
            cp16(aK + hb + i * 16 + r * 1024, gk + i * 16 + r * 1024);
            cp16(aV + hb + i * 16 + r * 1024, gv + i * 16 + r * 1024);
        }
        if (i < 8) {
            cp16(aVen + hs + i * 16, (const char*)(g_ven + vb + q * CH) + i * 16);
        } else if (i < 16) {
            cp16(aGam + hs + (i - 8) * 16, (const char*)(g_gam + vb + q * CH) + (i - 8) * 16);
        }
        asm volatile("cp.async.commit_group;" ::: "memory");
    };

    float2 M[32];
    #pragma unroll
    for (int c = 0; c < 32; c++) M[c] = make_float2(0.f, 0.f);

    stage(0);
    asm volatile("cp.async.wait_group 0;" ::: "memory");
    __syncthreads();

    // ---- peel step 0: M=0 -> d_0 = v_0 (uses sred parity 1) --------------
    float gdA = 0.0f, gdB;   // pending gd for steps t-2, t-1 of next block
    {
        const float d = sV[0][i];
        float z = d * d;
        z += __shfl_xor_sync(0xffffffffu, z, 1);
        z += __shfl_xor_sync(0xffffffffu, z, 2);
        z += __shfl_xor_sync(0xffffffffu, z, 4);
        z += __shfl_xor_sync(0xffffffffu, z, 8);
        z += __shfl_xor_sync(0xffffffffu, z, 16);
        if (lane == 0) sred[1][w] = make_float4(z, 0.f, 0.f, 0.f);
        __syncthreads();
        const float zt = sred[1][0].x + sred[1][1].x;
        gdB = (zt > sVen[0]) ? d : 0.0f;
    }

    // ---- main loop: 511 blocks of 2 steps, t = 1,3,...,1021 ---------------
    for (int j = 0; j < 511; j++) {
        const int t = 2 * j + 1;
        const int u = t + 1;
        const int ph = t & 31;
        if (ph == 3) {                        // stage next chunk (t-2 reads safe)
            const int qn = (t >> 5) + 1;
            if (qn < 32) stage(qn);
        }
        if (ph == 31) {                       // block reads slot u in new chunk
            asm volatile("cp.async.wait_group 0;" ::: "memory");
            __syncthreads();
        }

        const int sA = (j == 0) ? 0 : ((t - 2) & 63);   // gdA key (gdA=0 for j=0)
        const int sB = (t - 1) & 63;
        const int sT = t & 63;
        const int sU = u & 63;

        // ---- batch: apply both pending updates -> M_{t-1} ----------------
        {
            const float4* kA = reinterpret_cast<const float4*>(sK[sA]);
            const float4* kB = reinterpret_cast<const float4*>(sK[sB]);
            const float2 ga = make_float2(gdA, gdA);
            const float2 gb = make_float2(gdB, gdB);
            #pragma unroll
            for (int c = 0; c < 16; c++) {
                const float4 a = kA[c];
                const float4 bq = kB[c];
                float2 m0 = M[2 * c], m1 = M[2 * c + 1];
                m0 = fma2(ga, make_float2(a.x, a.y), m0);
                m1 = fma2(ga, make_float2(a.z, a.w), m1);
                m0 = fma2(gb, make_float2(bq.x, bq.y), m0);
                m1 = fma2(gb, make_float2(bq.z, bq.w), m1);
                M[2 * c] = m0; M[2 * c + 1] = m1;
            }
        }

        // ---- two matvecs with M_{t-1}: d_t and e_{t+1} -------------------
        float dt, eu;
        {
            const float4* kT = reinterpret_cast<const float4*>(sK[sT]);
            const float4* kU = reinterpret_cast<const float4*>(sK[sU]);
            float2 pt0 = make_float2(0.f, 0.f), pt1 = pt0, pt2 = pt0, pt3 = pt0;
            float2 pu0 = pt0, pu1 = pt0, pu2 = pt0, pu3 = pt0;
            #pragma unroll
            for (int c = 0; c < 16; c += 2) {
                const float4 a = kT[c];
                const float4 bq = kT[c + 1];
                pt0 = fma2(M[2 * c],     make_float2(a.x, a.y),  pt0);
                pt1 = fma2(M[2 * c + 1], make_float2(a.z, a.w),  pt1);
                pt2 = fma2(M[2 * c + 2], make_float2(bq.x, bq.y), pt2);
                pt3 = fma2(M[2 * c + 3], make_float2(bq.z, bq.w), pt3);
                const float4 a2 = kU[c];
                const float4 b2 = kU[c + 1];
                pu0 = fma2(M[2 * c],     make_float2(a2.x, a2.y), pu0);
                pu1 = fma2(M[2 * c + 1], make_float2(a2.z, a2.w), pu1);
                pu2 = fma2(M[2 * c + 2], make_float2(b2.x, b2.y), pu2);
                pu3 = fma2(M[2 * c + 3], make_float2(b2.z, b2.w), pu3);
            }
            dt = sV[sT][i] - (((pt0.x + pt0.y) + (pt1.x + pt1.y)) + ((pt2.x + pt2.y) + (pt3.x + pt3.y)));
            eu = sV[sU][i] - (((pu0.x + pu0.y) + (pu1.x + pu1.y)) + ((pu2.x + pu2.y) + (pu3.x + pu3.y)));
        }

        // ---- one reduction round for three scalars -----------------------
        float D = dt * dt;
        float E = eu * eu;
        float C = eu * dt;
        #pragma unroll
        for (int o = 1; o <= 16; o <<= 1) {
            D += __shfl_xor_sync(0xffffffffu, D, o);
            E += __shfl_xor_sync(0xffffffffu, E, o);
            C += __shfl_xor_sync(0xffffffffu, C, o);
        }
        const int pb = j & 1;
        if (lane == 0) sred[pb][w] = make_float4(D, E, C, 0.f);
        __syncthreads();                      // the ONLY barrier per 2 steps
        const float4 r0 = sred[pb][0];
        const float4 r1 = sred[pb][1];
        const float Dt = r0.x + r1.x;
        const float Et = r0.y + r1.y;
        const float Ct = r0.z + r1.z;

        // ---- resolve both gates scalar-side ------------------------------
        const float gam = sGam[sT];           // gamma_t
        const bool gt = Dt > sVen[sT];
        const float a = gt ? gam : 0.0f;
        const float z2 = fmaf(a, fmaf(gam, Dt, -2.0f * Ct), Et);
        const bool gu = z2 > sVen[sU];
        gdA = gt ? dt : 0.0f;
        const float du = fmaf(-a, dt, eu);    // exact per-component d_{t+1}
        gdB = gu ? du : 0.0f;
    }

    // ---- final pending updates (steps 1021, 1022) ------------------------
    {
        const float4* kA = reinterpret_cast<const float4*>(sK[1021 & 63]);
        const float4* kB = reinterpret_cast<const float4*>(sK[1022 & 63]);
        const float2 ga = make_float2(gdA, gdA);
        const float2 gb = make_float2(gdB, gdB);
        #pragma unroll
        for (int c = 0; c < 16; c++) {
            const float4 a = kA[c];
            const float4 bq = kB[c];
            float2 m0 = M[2 * c], m1 = M[2 * c + 1];
            m0 = fma2(ga, make_float2(a.x, a.y), m0);
            m1 = fma2(ga, make_float2(a.z, a.w), m1);
            m0 = fma2(gb, make_float2(bq.x, bq.y), m0);
            m1 = fma2(gb, make_float2(bq.z, bq.w), m1);
            M[2 * c] = m0; M[2 * c + 1] = m1;
        }
    }

    // -------- epilogue ----------------------------------------------------
    __syncthreads();
    sq[i] = g_q[(b << 6) + i];
    __syncthreads();
    float mq;
    {
        const float4* qp = reinterpret_cast<const float4*>(sq);
        float2 p0 = make_float2(0.f, 0.f), p1 = p0, p2 = p0, p3 = p0;
        #pragma unroll
        for (int c = 0; c < 16; c += 2) {
            const float4 wa = qp[c];
            const float4 wb = qp[c + 1];
            p0 = fma2(M[2 * c],     make_float2(wa.x, wa.y), p0);
            p1 = fma2(M[2 * c + 1], make_float2(wa.z, wa.w), p1);
            p2 = fma2(M[2 * c + 2], make_float2(wb.x, wb.y), p2);
            p3 = fma2(M[2 * c + 3], make_float2(wb.z, wb.w), p3);
        }
        mq = ((p0.x + p0.y) + (p1.x + p1.y)) + ((p2.x + p2.y) + (p3.x + p3.y));
    }
    __syncthreads();
    sr[i] = mq;
    __syncthreads();
    float r = rpb[i];
    for (int jj = 0; jj < 64; jj++) r = fmaf(sr[jj], rpW[jj * 64 + i], r);
    __syncthreads();
    sr[i] = r;
    __syncthreads();
    float o = outb[i];
    for (int jj = 0; jj < 64; jj++) o = fmaf(sr[jj], outW[jj * 64 + i], o);
    out[(b << 6) + i] = o;
}

// ---------------------------------------------------------------------------
extern "C" void kernel_launch(void* const* d_in, const int* in_sizes, int n_in,
                              void* d_out, int out_size)
{
    const int*   seq    = (const int*)  d_in[0];
    const float* embedW = (const float*)d_in[1];
    const float* W1     = (const float*)d_in[2];
    const float* b1     = (const float*)d_in[3];
    const float* W2     = (const float*)d_in[4];
    const float* b2     = (const float*)d_in[5];
    const float* lng    = (const float*)d_in[6];
    const float* lnb    = (const float*)d_in[7];
    const float* kpW    = (const float*)d_in[8];
    const float* vpW    = (const float*)d_in[9];
    const float* qpW    = (const float*)d_in[10];
    const float* rpW    = (const float*)d_in[11];
    const float* rpb    = (const float*)d_in[12];
    const float* outW   = (const float*)d_in[13];
    const float* outb   = (const float*)d_in[14];
    float* out = (float*)d_out;

    const int smem = SMEM_TOK_FLOATS * (int)sizeof(float);   // 201984 B
    cudaFuncSetAttribute(k_tokens, cudaFuncAttributeMaxDynamicSharedMemorySize, smem);

    k_tokens<<<512, 256, smem>>>(seq, embedW, W1, b1, W2, b2, lng, lnb, kpW, vpW, qpW);
    k_gamma<<<256, 256>>>();
    k_scan<<<64, 64>>>(rpW, rpb, outW, outb, out);
}

// round 15
// speedup vs baseline: 1.1620x; 1.0186x over previous
#include <cuda_runtime.h>
#include <cstdint>
#include <cstddef>

#define BB 64
#define LL 1024
#define HH 64
#define LM1 1023
#define CH 32            // scan staging chunk (steps)
#define TPC 128          // tokens per CTA in k_tokens
#define RP 132           // padded row length (floats) for transposed smem tiles

// Scratch (device globals — the allowed scratch mechanism). Zero-initialized.
__device__ float g_k  [BB * LM1 * HH + 2 * HH];   // pre-normalized keys (row-major)
__device__ float g_v  [BB * LM1 * HH + 2 * HH];   // values (row-major)
__device__ float g_ven[BB * 1024];                // 0.16*||v||^2
__device__ float g_gam[BB * 1024];                // gamma_t = kn_t . kn_{t+1}
__device__ float g_q  [BB * HH];

// Packed f32x2 FMA
__device__ __forceinline__ float2 fma2(float2 a, float2 b, float2 c) {
    float2 d;
    asm("fma.rn.f32x2 %0, %1, %2, %3;"
        : "=l"(*reinterpret_cast<unsigned long long*>(&d))
        : "l"(*reinterpret_cast<unsigned long long*>(&a)),
          "l"(*reinterpret_cast<unsigned long long*>(&b)),
          "l"(*reinterpret_cast<unsigned long long*>(&c)));
    return d;
}

__device__ __forceinline__ void cp16(uint32_t dst, const void* src) {
    asm volatile("cp.async.cg.shared.global [%0], [%1], 16;" :: "r"(dst), "l"(src));
}

// Shared-memory float offsets for k_tokens (total 50496 floats = 197.25 KB)
#define OFF_WA   0        /* 8192: W1 [64][128], later KV-combined [64][128] */
#define OFF_WB   8192     /* 8192: W2 [128][64] */
#define OFF_HT   16384    /* 8448: h^T / hn^T  [64][RP] */
#define OFF_ST   24832    /* 16896: s^T / kv^T [128][RP] */
#define OFF_FFT  41728    /* 8448: ff^T [64][RP] */
#define OFF_B1   50176    /* 128 */
#define OFF_B2   50304    /* 64 */
#define OFF_G    50368    /* 64 */
#define OFF_BT   50432    /* 64 */
#define SMEM_TOK_FLOATS 50496

// ---------------------------------------------------------------------------
// Kernel 1: cooperative register-tiled GEMM pipeline.
// 128 tokens/CTA, 256 threads. grid = 512 (B*L/TPC).
// A-operand tiling: each thread owns float4 columns {j, j+16} (j = tid&15)
// -> conflict-free LDS.128 phases (f mod 8 distinct within each quarter-warp).
// ---------------------------------------------------------------------------
__global__ __launch_bounds__(256, 1)
void k_tokens(const int*   __restrict__ seq,
              const float* __restrict__ embedW,
              const float* __restrict__ W1,   // [64][128]
              const float* __restrict__ b1,   // [128]
              const float* __restrict__ W2,   // [128][64]
              const float* __restrict__ b2,   // [64]
              const float* __restrict__ lng,
              const float* __restrict__ lnb,
              const float* __restrict__ kpW,  // [64][64]
              const float* __restrict__ vpW,  // [64][64]
              const float* __restrict__ qpW)  // [64][64]
{
    extern __shared__ float sm[];
    const int tid = threadIdx.x;
    const int cta = blockIdx.x;
    const int b = cta >> 3;
    const int tbase = (cta & 7) * TPC;

    const uint32_t smA = (uint32_t)__cvta_generic_to_shared(sm + OFF_WA);
    const uint32_t smB = (uint32_t)__cvta_generic_to_shared(sm + OFF_WB);

    #pragma unroll
    for (int r = 0; r < 8; r++) {
        cp16(smA + (tid + 256 * r) * 16, (const char*)W1 + (tid + 256 * r) * 16);
        cp16(smB + (tid + 256 * r) * 16, (const char*)W2 + (tid + 256 * r) * 16);
    }
    asm volatile("cp.async.commit_group;" ::: "memory");

    if (tid < 128) sm[OFF_B1 + tid] = b1[tid];
    if (tid < 64) {
        sm[OFF_B2 + tid] = b2[tid];
        sm[OFF_G  + tid] = lng[tid];
        sm[OFF_BT + tid] = lnb[tid];
    }

    const int tok  = tid >> 1;
    const int half = tid & 1;
    {
        const int sidx = seq[(b << 10) + tbase + tok];
        const float4* e4 = reinterpret_cast<const float4*>(embedW + (sidx << 6) + half * 32);
        float* ht = sm + OFF_HT;
        #pragma unroll
        for (int r = 0; r < 8; r++) {
            float4 w = e4[r];
            int k = half * 32 + r * 4;
            ht[(k + 0) * RP + tok] = w.x;
            ht[(k + 1) * RP + tok] = w.y;
            ht[(k + 2) * RP + tok] = w.z;
            ht[(k + 3) * RP + tok] = w.w;
        }
    }
    asm volatile("cp.async.wait_group 0;" ::: "memory");
    __syncthreads();

    // ---- GEMM1: s[m][n] = relu(h[m][:]@W1[:][n] + b1), write s^T ---------
    // Thread m-tile: float4 columns {fj, fj+16}  (m-values 4fj..4fj+3 and 64+4fj..)
    {
        const int fj = tid & 15;
        const int n0 = (tid >> 4) * 8;
        float2 c1[8][4];
        #pragma unroll
        for (int ni = 0; ni < 8; ni++)
            #pragma unroll
            for (int mj = 0; mj < 4; mj++) c1[ni][mj] = make_float2(0.f, 0.f);

        const float4* ht4 = reinterpret_cast<const float4*>(sm + OFF_HT);
        const float4* w14 = reinterpret_cast<const float4*>(sm + OFF_WA);
        #pragma unroll 4
        for (int k = 0; k < 64; k++) {
            const float4 a0 = ht4[k * (RP / 4) + fj];
            const float4 a1 = ht4[k * (RP / 4) + fj + 16];
            const float2 am[4] = { {a0.x, a0.y}, {a0.z, a0.w}, {a1.x, a1.y}, {a1.z, a1.w} };
            const float4 b0 = w14[k * 32 + n0 / 4];
            const float4 bq = w14[k * 32 + n0 / 4 + 1];
            const float bn[8] = { b0.x, b0.y, b0.z, b0.w, bq.x, bq.y, bq.z, bq.w };
            #pragma unroll
            for (int ni = 0; ni < 8; ni++) {
                const float2 bb = make_float2(bn[ni], bn[ni]);
                #pragma unroll
                for (int mj = 0; mj < 4; mj++)
                    c1[ni][mj] = fma2(bb, am[mj], c1[ni][mj]);
            }
        }
        float4* st4 = reinterpret_cast<float4*>(sm + OFF_ST);
        #pragma unroll
        for (int ni = 0; ni < 8; ni++) {
            const float bb = sm[OFF_B1 + n0 + ni];
            float2 r0 = c1[ni][0], r1 = c1[ni][1], r2 = c1[ni][2], r3 = c1[ni][3];
            r0.x = fmaxf(r0.x + bb, 0.f); r0.y = fmaxf(r0.y + bb, 0.f);
            r1.x = fmaxf(r1.x + bb, 0.f); r1.y = fmaxf(r1.y + bb, 0.f);
            r2.x = fmaxf(r2.x + bb, 0.f); r2.y = fmaxf(r2.y + bb, 0.f);
            r3.x = fmaxf(r3.x + bb, 0.f); r3.y = fmaxf(r3.y + bb, 0.f);
            st4[(n0 + ni) * (RP / 4) + fj]      = make_float4(r0.x, r0.y, r1.x, r1.y);
            st4[(n0 + ni) * (RP / 4) + fj + 16] = make_float4(r2.x, r2.y, r3.x, r3.y);
        }
    }
    __syncthreads();

    // ---- prefetch KV-combined weights [64][128] (2048 float4s) -----------
    {
        #pragma unroll
        for (int r = 0; r < 8; r++) {
            const int f = tid + 256 * r;        // 0..2047
            const int k = f >> 5;               // 0..63
            const int c4 = f & 31;
            const char* src = (c4 < 16)
                ? (const char*)kpW + (k * 16 + c4) * 16
                : (const char*)vpW + (k * 16 + (c4 - 16)) * 16;
            cp16(smA + f * 16, src);
        }
        asm volatile("cp.async.commit_group;" ::: "memory");
    }

    // ---- GEMM2: ff[m][n] = s[m][:]@W2[:][n] + b2, write ff^T -------------
    {
        const int m0 = (tid >> 4) * 8;
        const int n0 = (tid & 15) * 4;
        float2 c2[4][4];
        #pragma unroll
        for (int ni = 0; ni < 4; ni++)
            #pragma unroll
            for (int mj = 0; mj < 4; mj++) c2[ni][mj] = make_float2(0.f, 0.f);

        const float4* st4 = reinterpret_cast<const float4*>(sm + OFF_ST);
        const float4* w24 = reinterpret_cast<const float4*>(sm + OFF_WB);
        #pragma unroll 4
        for (int k = 0; k < 128; k++) {
            const float4 a0 = st4[k * (RP / 4) + m0 / 4];
            const float4 a1 = st4[k * (RP / 4) + m0 / 4 + 1];
            const float2 am[4] = { {a0.x, a0.y}, {a0.z, a0.w}, {a1.x, a1.y}, {a1.z, a1.w} };
            const float4 b0 = w24[k * 16 + n0 / 4];
            const float bn[4] = { b0.x, b0.y, b0.z, b0.w };
            #pragma unroll
            for (int ni = 0; ni < 4; ni++) {
                const float2 bb = make_float2(bn[ni], bn[ni]);
                #pragma unroll
                for (int mj = 0; mj < 4; mj++)
                    c2[ni][mj] = fma2(bb, am[mj], c2[ni][mj]);
            }
        }
        float4* ff4 = reinterpret_cast<float4*>(sm + OFF_FFT);
        #pragma unroll
        for (int ni = 0; ni < 4; ni++) {
            const float bb = sm[OFF_B2 + n0 + ni];
            float2 r0 = c2[ni][0], r1 = c2[ni][1], r2 = c2[ni][2], r3 = c2[ni][3];
            r0.x += bb; r0.y += bb; r1.x += bb; r1.y += bb;
            r2.x += bb; r2.y += bb; r3.x += bb; r3.y += bb;
            ff4[(n0 + ni) * (RP / 4) + m0 / 4]     = make_float4(r0.x, r0.y, r1.x, r1.y);
            ff4[(n0 + ni) * (RP / 4) + m0 / 4 + 1] = make_float4(r2.x, r2.y, r3.x, r3.y);
        }
    }
    __syncthreads();

    // ---- LayerNorm per token (2 threads/token, partner shfl) -------------
    {
        float x[32];
        const float* ht = sm + OFF_HT;
        const float* ff = sm + OFF_FFT;
        #pragma unroll
        for (int j = 0; j < 32; j++) {
            const int k = half * 32 + j;
            x[j] = ht[k * RP + tok] + ff[k * RP + tok];
        }
        float s1 = 0.f;
        #pragma unroll
        for (int j = 0; j < 32; j++) s1 += x[j];
        s1 += __shfl_xor_sync(0xffffffffu, s1, 1);
        const float mu = s1 * (1.0f / 64.0f);
        float s2 = 0.f;
        #pragma unroll
        for (int j = 0; j < 32; j++) { const float dx = x[j] - mu; s2 += dx * dx; }
        s2 += __shfl_xor_sync(0xffffffffu, s2, 1);
        const float inv = 1.0f / sqrtf(s2 * (1.0f / 64.0f) + 1e-5f);
        float* hw = sm + OFF_HT;
        #pragma unroll
        for (int j = 0; j < 32; j++) {
            const int k = half * 32 + j;
            hw[k * RP + tok] = (x[j] - mu) * inv * sm[OFF_G + k] + sm[OFF_BT + k];
        }
    }
    asm volatile("cp.async.wait_group 0;" ::: "memory");
    __syncthreads();

    // ---- GEMM3: kv[m][n] = hn[m][:]@KV[:][n]  (n<64: K, n>=64: V) --------
    // Same conflict-free split m-tile {fj, fj+16}.
    {
        const int fj = tid & 15;
        const int n0 = (tid >> 4) * 8;
        float2 c3[8][4];
        #pragma unroll
        for (int ni = 0; ni < 8; ni++)
            #pragma unroll
            for (int mj = 0; mj < 4; mj++) c3[ni][mj] = make_float2(0.f, 0.f);

        const float4* ht4 = reinterpret_cast<const float4*>(sm + OFF_HT);
        const float4* wk4 = reinterpret_cast<const float4*>(sm + OFF_WA);
        #pragma unroll 4
        for (int k = 0; k < 64; k++) {
            const float4 a0 = ht4[k * (RP / 4) + fj];
            const float4 a1 = ht4[k * (RP / 4) + fj + 16];
            const float2 am[4] = { {a0.x, a0.y}, {a0.z, a0.w}, {a1.x, a1.y}, {a1.z, a1.w} };
            const float4 b0 = wk4[k * 32 + n0 / 4];
            const float4 bq = wk4[k * 32 + n0 / 4 + 1];
            const float bn[8] = { b0.x, b0.y, b0.z, b0.w, bq.x, bq.y, bq.z, bq.w };
            #pragma unroll
            for (int ni = 0; ni < 8; ni++) {
                const float2 bb = make_float2(bn[ni], bn[ni]);
                #pragma unroll
                for (int mj = 0; mj < 4; mj++)
                    c3[ni][mj] = fma2(bb, am[mj], c3[ni][mj]);
            }
        }
        float4* kv4 = reinterpret_cast<float4*>(sm + OFF_ST);
        #pragma unroll
        for (int ni = 0; ni < 8; ni++) {
            const float2 r0 = c3[ni][0], r1 = c3[ni][1], r2 = c3[ni][2], r3 = c3[ni][3];
            kv4[(n0 + ni) * (RP / 4) + fj]      = make_float4(r0.x, r0.y, r1.x, r1.y);
            kv4[(n0 + ni) * (RP / 4) + fj + 16] = make_float4(r2.x, r2.y, r3.x, r3.y);
        }
    }
    __syncthreads();

    // ---- k-normalize, ven, stores (2 threads/token) ----------------------
    {
        const int t = tbase + tok;
        const float* kv = sm + OFF_ST;
        float kvv[32];
        float nk = 0.f;
        #pragma unroll
        for (int j = 0; j < 32; j++) {
            kvv[j] = kv[(half * 32 + j) * RP + tok];
            nk = fmaf(kvv[j], kvv[j], nk);
        }
        nk += __shfl_xor_sync(0xffffffffu, nk, 1);
        const float kinv = 1.0f / fmaxf(sqrtf(nk), 1e-12f);
        if (t < LM1) {
            const size_t base = ((size_t)(b * LM1 + t)) << 6;
            float4* gk4 = reinterpret_cast<float4*>(g_k + base + half * 32);
            #pragma unroll
            for (int j4 = 0; j4 < 8; j4++) {
                gk4[j4] = make_float4(kvv[4 * j4] * kinv, kvv[4 * j4 + 1] * kinv,
                                      kvv[4 * j4 + 2] * kinv, kvv[4 * j4 + 3] * kinv);
            }
        }
        float nv = 0.f;
        #pragma unroll
        for (int j = 0; j < 32; j++) {
            kvv[j] = kv[(64 + half * 32 + j) * RP + tok];
            nv = fmaf(kvv[j], kvv[j], nv);
        }
        const float nvt = nv + __shfl_xor_sync(0xffffffffu, nv, 1);
        if (t < LM1) {
            const size_t base = ((size_t)(b * LM1 + t)) << 6;
            float4* gv4 = reinterpret_cast<float4*>(g_v + base + half * 32);
            #pragma unroll
            for (int j4 = 0; j4 < 8; j4++) {
                gv4[j4] = make_float4(kvv[4 * j4], kvv[4 * j4 + 1],
                                      kvv[4 * j4 + 2], kvv[4 * j4 + 3]);
            }
            if (half == 0) g_ven[(b << 10) + t] = 0.16f * nvt;
        }
    }

    // ---- q projection (only CTAs containing t = 1023; token 127) ---------
    if ((cta & 7) == 7 && tid < 64) {
        const float* ht = sm + OFF_HT;
        float a0 = 0.f, a1 = 0.f, a2 = 0.f, a3 = 0.f;
        #pragma unroll 8
        for (int k = 0; k < 64; k += 4) {
            a0 = fmaf(ht[(k + 0) * RP + 127], __ldg(qpW + (k + 0) * 64 + tid), a0);
            a1 = fmaf(ht[(k + 1) * RP + 127], __ldg(qpW + (k + 1) * 64 + tid), a1);
            a2 = fmaf(ht[(k + 2) * RP + 127], __ldg(qpW + (k + 2) * 64 + tid), a2);
            a3 = fmaf(ht[(k + 3) * RP + 127], __ldg(qpW + (k + 3) * 64 + tid), a3);
        }
        g_q[(b << 6) + tid] = (a0 + a1) + (a2 + a3);
    }
}

// ---------------------------------------------------------------------------
// Kernel 1b: adjacent-key dots  gamma[b][t] = kn_t . kn_{t+1}
// ---------------------------------------------------------------------------
__global__ __launch_bounds__(256, 1)
void k_gamma()
{
    const int idx = blockIdx.x * 256 + threadIdx.x;
    const int b = idx >> 10;
    const int t = idx & 1023;
    float g = 0.0f;
    if (t <= LM1 - 2) {
        const float4* a = reinterpret_cast<const float4*>(g_k + (((size_t)(b * LM1 + t)) << 6));
        const float4* c = a + 16;
        float s0 = 0.f, s1 = 0.f, s2 = 0.f, s3 = 0.f;
        #pragma unroll
        for (int k = 0; k < 16; k += 2) {
            float4 x0 = a[k],     y0 = c[k];
            float4 x1 = a[k + 1], y1 = c[k + 1];
            s0 = fmaf(x0.x, y0.x, fmaf(x0.y, y0.y, s0));
            s1 = fmaf(x0.z, y0.z, fmaf(x0.w, y0.w, s1));
            s2 = fmaf(x1.x, y1.x, fmaf(x1.y, y1.y, s2));
            s3 = fmaf(x1.z, y1.z, fmaf(x1.w, y1.w, s3));
        }
        g = (s0 + s1) + (s2 + s3);
    }
    g_gam[(b << 10) + t] = g;
}

// ---------------------------------------------------------------------------
// Kernel 2: gated fast-weight scan — 2 gates per serial round (R9, best).
// ---------------------------------------------------------------------------
__global__ __launch_bounds__(64, 1)
void k_scan(const float* __restrict__ rpW,
            const float* __restrict__ rpb,
            const float* __restrict__ outW,
            const float* __restrict__ outb,
            float* __restrict__ out)
{
    __shared__ float  sK[2 * CH][64];
    __shared__ float  sV[2 * CH][64];
    __shared__ float  sVen[2 * CH];
    __shared__ float  sGam[2 * CH];
    __shared__ float4 sred[2][2];     // (D,E,C,-) per warp, parity-buffered
    __shared__ float  sq[64];
    __shared__ float  sr[64];

    const int i = threadIdx.x;
    const int b = blockIdx.x;
    const int lane = i & 31, w = i >> 5;

    const size_t base = (size_t)b * LM1 * 64;
    const int vb = b << 10;

    const uint32_t aK   = (uint32_t)__cvta_generic_to_shared(&sK[0][0]);
    const uint32_t aV   = (uint32_t)__cvta_generic_to_shared(&sV[0][0]);
    const uint32_t aVen = (uint32_t)__cvta_generic_to_shared(&sVen[0]);
    const uint32_t aGam = (uint32_t)__cvta_generic_to_shared(&sGam[0]);

    auto stage = [&](int q) {
        const int hb = (q & 1) * (CH * 64 * 4);
        const int hs = (q & 1) * (CH * 4);
        const char* gk = (const char*)(g_k + base) + ((size_t)q << 13);
        const char* gv = (const char*)(g_v + base) + ((size_t)q << 13);
        #pragma unroll
        for (int r = 0; r < 8; r++) {
            cp16(aK + hb + i * 16 + r * 1024, gk + i * 16 + r * 1024);
            cp16(aV + hb + i * 16 + r * 1024, gv + i * 16 + r * 1024);
        }
        if (i < 8) {
            cp16(aVen + hs + i * 16, (const char*)(g_ven + vb + q * CH) + i * 16);
        } else if (i < 16) {
            cp16(aGam + hs + (i - 8) * 16, (const char*)(g_gam + vb + q * CH) + (i - 8) * 16);
        }
        asm volatile("cp.async.commit_group;" ::: "memory");
    };

    float2 M[32];
    #pragma unroll
    for (int c = 0; c < 32; c++) M[c] = make_float2(0.f, 0.f);

    stage(0);
    asm volatile("cp.async.wait_group 0;" ::: "memory");
    __syncthreads();

    // ---- peel step 0: M=0 -> d_0 = v_0 (uses sred parity 1) --------------
    float gdA = 0.0f, gdB;   // pending gd for steps t-2, t-1 of next block
    {
        const float d = sV[0][i];
        float z = d * d;
        z += __shfl_xor_sync(0xffffffffu, z, 1);
        z += __shfl_xor_sync(0xffffffffu, z, 2);
        z += __shfl_xor_sync(0xffffffffu, z, 4);
        z += __shfl_xor_sync(0xffffffffu, z, 8);
        z += __shfl_xor_sync(0xffffffffu, z, 16);
        if (lane == 0) sred[1][w] = make_float4(z, 0.f, 0.f, 0.f);
        __syncthreads();
        const float zt = sred[1][0].x + sred[1][1].x;
        gdB = (zt > sVen[0]) ? d : 0.0f;
    }

    // ---- main loop: 511 blocks of 2 steps, t = 1,3,...,1021 ---------------
    for (int j = 0; j < 511; j++) {
        const int t = 2 * j + 1;
        const int u = t + 1;
        const int ph = t & 31;
        if (ph == 3) {                        // stage next chunk (t-2 reads safe)
            const int qn = (t >> 5) + 1;
            if (qn < 32) stage(qn);
        }
        if (ph == 31) {                       // block reads slot u in new chunk
            asm volatile("cp.async.wait_group 0;" ::: "memory");
            __syncthreads();
        }

        const int sA = (j == 0) ? 0 : ((t - 2) & 63);   // gdA key (gdA=0 for j=0)
        const int sB = (t - 1) & 63;
        const int sT = t & 63;
        const int sU = u & 63;

        // ---- batch: apply both pending updates -> M_{t-1} ----------------
        {
            const float4* kA = reinterpret_cast<const float4*>(sK[sA]);
            const float4* kB = reinterpret_cast<const float4*>(sK[sB]);
            const float2 ga = make_float2(gdA, gdA);
            const float2 gb = make_float2(gdB, gdB);
            #pragma unroll
            for (int c = 0; c < 16; c++) {
                const float4 a = kA[c];
                const float4 bq = kB[c];
                float2 m0 = M[2 * c], m1 = M[2 * c + 1];
                m0 = fma2(ga, make_float2(a.x, a.y), m0);
                m1 = fma2(ga, make_float2(a.z, a.w), m1);
                m0 = fma2(gb, make_float2(bq.x, bq.y), m0);
                m1 = fma2(gb, make_float2(bq.z, bq.w), m1);
                M[2 * c] = m0; M[2 * c + 1] = m1;
            }
        }

        // ---- two matvecs with M_{t-1}: d_t and e_{t+1} -------------------
        float dt, eu;
        {
            const float4* kT = reinterpret_cast<const float4*>(sK[sT]);
            const float4* kU = reinterpret_cast<const float4*>(sK[sU]);
            float2 pt0 = make_float2(0.f, 0.f), pt1 = pt0, pt2 = pt0, pt3 = pt0;
            float2 pu0 = pt0, pu1 = pt0, pu2 = pt0, pu3 = pt0;
            #pragma unroll
            for (int c = 0; c < 16; c += 2) {
                const float4 a = kT[c];
                const float4 bq = kT[c + 1];
                pt0 = fma2(M[2 * c],     make_float2(a.x, a.y),  pt0);
                pt1 = fma2(M[2 * c + 1], make_float2(a.z, a.w),  pt1);
                pt2 = fma2(M[2 * c + 2], make_float2(bq.x, bq.y), pt2);
                pt3 = fma2(M[2 * c + 3], make_float2(bq.z, bq.w), pt3);
                const float4 a2 = kU[c];
                const float4 b2 = kU[c + 1];
                pu0 = fma2(M[2 * c],     make_float2(a2.x, a2.y), pu0);
                pu1 = fma2(M[2 * c + 1], make_float2(a2.z, a2.w), pu1);
                pu2 = fma2(M[2 * c + 2], make_float2(b2.x, b2.y), pu2);
                pu3 = fma2(M[2 * c + 3], make_float2(b2.z, b2.w), pu3);
            }
            dt = sV[sT][i] - (((pt0.x + pt0.y) + (pt1.x + pt1.y)) + ((pt2.x + pt2.y) + (pt3.x + pt3.y)));
            eu = sV[sU][i] - (((pu0.x + pu0.y) + (pu1.x + pu1.y)) + ((pu2.x + pu2.y) + (pu3.x + pu3.y)));
        }

        // ---- one reduction round for three scalars -----------------------
        float D = dt * dt;
        float E = eu * eu;
        float C = eu * dt;
        #pragma unroll
        for (int o = 1; o <= 16; o <<= 1) {
            D += __shfl_xor_sync(0xffffffffu, D, o);
            E += __shfl_xor_sync(0xffffffffu, E, o);
            C += __shfl_xor_sync(0xffffffffu, C, o);
        }
        const int pb = j & 1;
        if (lane == 0) sred[pb][w] = make_float4(D, E, C, 0.f);
        __syncthreads();                      // the ONLY barrier per 2 steps
        const float4 r0 = sred[pb][0];
        const float4 r1 = sred[pb][1];
        const float Dt = r0.x + r1.x;
        const float Et = r0.y + r1.y;
        const float Ct = r0.z + r1.z;

        // ---- resolve both gates scalar-side ------------------------------
        const float gam = sGam[sT];           // gamma_t
        const bool gt = Dt > sVen[sT];
        const float a = gt ? gam : 0.0f;
        const float z2 = fmaf(a, fmaf(gam, Dt, -2.0f * Ct), Et);
        const bool gu = z2 > sVen[sU];
        gdA = gt ? dt : 0.0f;
        const float du = fmaf(-a, dt, eu);    // exact per-component d_{t+1}
        gdB = gu ? du : 0.0f;
    }

    // ---- final pending updates (steps 1021, 1022) ------------------------
    {
        const float4* kA = reinterpret_cast<const float4*>(sK[1021 & 63]);
        const float4* kB = reinterpret_cast<const float4*>(sK[1022 & 63]);
        const float2 ga = make_float2(gdA, gdA);
        const float2 gb = make_float2(gdB, gdB);
        #pragma unroll
        for (int c = 0; c < 16; c++) {
            const float4 a = kA[c];
            const float4 bq = kB[c];
            float2 m0 = M[2 * c], m1 = M[2 * c + 1];
            m0 = fma2(ga, make_float2(a.x, a.y), m0);
            m1 = fma2(ga, make_float2(a.z, a.w), m1);
            m0 = fma2(gb, make_float2(bq.x, bq.y), m0);
            m1 = fma2(gb, make_float2(bq.z, bq.w), m1);
            M[2 * c] = m0; M[2 * c + 1] = m1;
        }
    }

    // -------- epilogue ----------------------------------------------------
    __syncthreads();
    sq[i] = g_q[(b << 6) + i];
    __syncthreads();
    float mq;
    {
        const float4* qp = reinterpret_cast<const float4*>(sq);
        float2 p0 = make_float2(0.f, 0.f), p1 = p0, p2 = p0, p3 = p0;
        #pragma unroll
        for (int c = 0; c < 16; c += 2) {
            const float4 wa = qp[c];
            const float4 wb = qp[c + 1];
            p0 = fma2(M[2 * c],     make_float2(wa.x, wa.y), p0);
            p1 = fma2(M[2 * c + 1], make_float2(wa.z, wa.w), p1);
            p2 = fma2(M[2 * c + 2], make_float2(wb.x, wb.y), p2);
            p3 = fma2(M[2 * c + 3], make_float2(wb.z, wb.w), p3);
        }
        mq = ((p0.x + p0.y) + (p1.x + p1.y)) + ((p2.x + p2.y) + (p3.x + p3.y));
    }
    __syncthreads();
    sr[i] = mq;
    __syncthreads();
    float r = rpb[i];
    for (int jj = 0; jj < 64; jj++) r = fmaf(sr[jj], rpW[jj * 64 + i], r);
    __syncthreads();
    sr[i] = r;
    __syncthreads();
    float o = outb[i];
    for (int jj = 0; jj < 64; jj++) o = fmaf(sr[jj], outW[jj * 64 + i], o);
    out[(b << 6) + i] = o;
}

// ---------------------------------------------------------------------------
extern "C" void kernel_launch(void* const* d_in, const int* in_sizes, int n_in,
                              void* d_out, int out_size)
{
    const int*   seq    = (const int*)  d_in[0];
    const float* embedW = (const float*)d_in[1];
    const float* W1     = (const float*)d_in[2];
    const float* b1     = (const float*)d_in[3];
    const float* W2     = (const float*)d_in[4];
    const float* b2     = (const float*)d_in[5];
    const float* lng    = (const float*)d_in[6];
    const float* lnb    = (const float*)d_in[7];
    const float* kpW    = (const float*)d_in[8];
    const float* vpW    = (const float*)d_in[9];
    const float* qpW    = (const float*)d_in[10];
    const float* rpW    = (const float*)d_in[11];
    const float* rpb    = (const float*)d_in[12];
    const float* outW   = (const float*)d_in[13];
    const float* outb   = (const float*)d_in[14];
    float* out = (float*)d_out;

    const int smem = SMEM_TOK_FLOATS * (int)sizeof(float);   // 201984 B
    cudaFuncSetAttribute(k_tokens, cudaFuncAttributeMaxDynamicSharedMemorySize, smem);

    k_tokens<<<512, 256, smem>>>(seq, embedW, W1, b1, W2, b2, lng, lnb, kpW, vpW, qpW);
    k_gamma<<<256, 256>>>();
    k_scan<<<64, 64>>>(rpW, rpb, outW, outb, out);
}